// round 14
// baseline (speedup 1.0000x reference)
#include <cuda_runtime.h>

#define DIMN 2048
#define DIM2 (DIMN * DIMN)            // 4,194,304 = 1<<22
#define THETA 1e-18
#define TH2   1e-36
#define ZETA2 1.6449340668482264365   // pi^2/6
#define REGC  1e-15
#define PI_D  3.141592653589793

// first 50 primes (all <= 229)
__constant__ int c_p50[50] = {
    2,3,5,7,11,13,17,19,23,29,31,37,41,43,47,53,59,61,67,71,
    73,79,83,89,97,101,103,107,109,113,127,131,137,139,149,151,157,163,167,173,
    179,181,191,193,197,199,211,223,227,229
};

__device__ __forceinline__ bool isp50(int n) {
    if (n < 2 || n > 229) return false;
    for (int t = 0; t < 50; ++t)
        if (c_p50[t] == n) return true;
    return false;
}

// Arnold matrix entry A[i][k] (real symmetric, half-bandwidth 2).
__device__ __forceinline__ double aent(int i, int k) {
    int d = k - i; if (d < 0) d = -d;
    if (d == 0) return 1.0 + THETA * cos(2.0 * PI_D * (double)i / (double)DIMN);
    if (d == 1) { int m = i < k ? i : k; return THETA * sin(PI_D * (2.0 * m + 1.0) / (double)DIMN); }
    if (d == 2) return TH2 * exp(-0.2);
    return 0.0;
}

// H[i][j] in fp64. Out-of-band (|i-j|>5): exact zero (the reference's dense
// matmuls sum 0*x there). In-band: banded triple product A*herm(H0)*A^T
// + Hermitian algebra term * |s| + REG on the diagonal.
__device__ __forceinline__ void helem(int i, int j, double sr, double si,
                                      double& re, double& im)
{
    re = 0.0; im = 0.0;
    int off = j - i;
    if (off < -5 || off > 5) return;

    int ulo = i - 2 < 0 ? 0 : i - 2;
    int uhi = i + 2 > DIMN - 1 ? DIMN - 1 : i + 2;
    int vlo0 = j - 2 < 0 ? 0 : j - 2;
    int vhi0 = j + 2 > DIMN - 1 ? DIMN - 1 : j + 2;

    for (int u = ulo; u <= uhi; ++u) {
        double ai = aent(i, u);
        int vlo = vlo0 > u - 1 ? vlo0 : u - 1;
        int vhi = vhi0 < u + 1 ? vhi0 : u + 1;
        for (int v = vlo; v <= vhi; ++v) {
            double aj = aent(j, v);
            double w = ai * aj;
            if (u == v) {
                double nn = (double)(u + 1);
                double ln = log(nn);
                double hr = exp(-sr * ln) * cos(si * ln);   // Re(n^{-s})
                if (isp50(u + 1)) hr += THETA * ln * ZETA2;
                re += w * hr;
            } else if (v == u + 1) {
                if (isp50(u + 1)) im += w * (0.5 * THETA * log((double)(u + 1)));
            } else { // u == v + 1
                if (isp50(u)) im -= w * (0.5 * THETA * log((double)u));
            }
        }
    }

    double sabs = sqrt(sr * sr + si * si);
    if (off == 1)       im += THETA * sabs;
    else if (off == -1) im -= THETA * sabs;
    else if (off == 2 || off == -2) {
        int m = i < j ? i : j;
        re += TH2 * exp(-(double)m / 100.0) * sabs;
    }
    if (off == 0) re += REGC;
}

// Layout P: planar float32 [real matrix (DIM2) ; imag matrix (DIM2)]
__global__ void __launch_bounds__(256)
nkaro_planar(const float* __restrict__ srp, const float* __restrict__ sip,
             float* __restrict__ out)
{
    unsigned idx = blockIdx.x * 256u + threadIdx.x;     // grid covers 2*DIM2 exactly
    unsigned k = idx & (DIM2 - 1u);
    int plane = (int)(idx >> 22);
    int i = (int)(k >> 11);
    int j = (int)(k & (DIMN - 1));

    int off = j - i;
    if (off < -5 || off > 5) { out[idx] = 0.0f; return; }

    double re, im;
    helem(i, j, (double)(*srp), (double)(*sip), re, im);
    out[idx] = (float)(plane ? im : re);
}

// Layout R: real part only, float32, DIM2 elements
__global__ void __launch_bounds__(256)
nkaro_real(const float* __restrict__ srp, const float* __restrict__ sip,
           float* __restrict__ out, unsigned total)
{
    unsigned idx = blockIdx.x * 256u + threadIdx.x;
    if (idx >= total) return;
    int i = (int)(idx >> 11);
    int j = (int)(idx & (DIMN - 1));

    int off = j - i;
    if (off < -5 || off > 5) { out[idx] = 0.0f; return; }

    double re, im;
    helem(i, j, (double)(*srp), (double)(*sip), re, im);
    out[idx] = (float)re;
}

extern "C" void kernel_launch(void* const* d_in, const int* in_sizes, int n_in,
                              void* d_out, int out_size)
{
    (void)in_sizes; (void)n_in;
    const float* sr = (const float*)d_in[0];
    const float* si = (const float*)d_in[1];
    float* out = (float*)d_out;

    if (out_size == 2 * DIM2) {
        // complex stored planar: [real ; imag]
        unsigned blocks = (2u * DIM2) / 256u;
        nkaro_planar<<<blocks, 256>>>(sr, si, out);
    } else {
        // real part only (or unknown size: bounds-guarded)
        unsigned total = (unsigned)out_size;
        unsigned blocks = (total + 255u) / 256u;
        if (blocks == 0) blocks = 1;
        nkaro_real<<<blocks, 256>>>(sr, si, out, total);
    }
}

// round 16
// speedup vs baseline: 14.3555x; 14.3555x over previous
#include <cuda_runtime.h>

#define DIMN 2048
#define DIM2 (DIMN * DIMN)            // 4,194,304

// Precomputed zeta diagonal: exp(-sr*ln n)*cos(si*ln n), n = i+1, in fp64.
__device__ double d_diag[DIMN];

// Bitmask of the first 50 primes (all <= 229): bit n set iff n prime.
__constant__ unsigned c_pmask[8] = {
    0xA08A28ACu, 0x28028A20u, 0x02088288u, 0x800228A2u,
    0x20A00A08u, 0x00282088u, 0x000800A2u, 0x00000028u
};

__device__ __forceinline__ bool ispf(int n) {
    return (unsigned)n < 230u && ((c_pmask[n >> 5] >> (n & 31)) & 1u);
}

// Arnold entry in fp32. Diagonal: 1 + 1e-18*cos == 1.0 exactly (even in fp64,
// since 1e-18 < eps(1)/2), so return 1.0f.
__device__ __forceinline__ float aentf(int i, int k) {
    int d = k - i; if (d < 0) d = -d;
    if (d == 0) return 1.0f;
    if (d == 1) {
        int m = i < k ? i : k;
        return 1e-18f * sinf(3.14159265358979f * (2.0f * (float)m + 1.0f) * (1.0f / (float)DIMN));
    }
    return 8.1873075e-37f;   // theta^2 * exp(-0.2)
}

// Real part of H[i][j] for |i-j| <= 5.
// re = sum_u A[i,u]*A[j,u]*hr(u)  (only u==v diag of herm(H0) is real)
//      + algebra real part (|off|==2) * |s| + REG on diagonal.
// Imaginary H0 prime off-diagonals and the |off|==1 algebra term contribute
// only to Im(H) and are dropped (output is the real part).
__device__ __forceinline__ float band_re(int i, int j, float sabs) {
    int mx = i > j ? i : j;
    int mn = i < j ? i : j;
    int lo = mx - 2 < 0 ? 0 : mx - 2;
    int hi = mn + 2 > DIMN - 1 ? DIMN - 1 : mn + 2;

    float acc = 0.0f;
    for (int u = lo; u <= hi; ++u) {
        float w = aentf(i, u) * aentf(j, u);
        if (w != 0.0f) {
            float hr = (float)d_diag[u];
            if (ispf(u + 1))
                hr += 1e-18f * logf((float)(u + 1)) * 1.64493406684822644f; // theta*ln p*zeta2
            acc += w * hr;
        }
    }
    int off = j - i;
    if (off == 2 || off == -2)
        acc += 1e-36f * expf(-(float)mn * 0.01f) * sabs;
    if (off == 0)
        acc += 1e-15f;
    return acc;
}

// Tiny fp64 kernel: 2048 threads (64 warps chip-wide) compute the accurate
// zeta diagonal. Keeps all fp64 transcendentals out of the wide kernel.
__global__ void __launch_bounds__(256)
nkaro_diag(const float* __restrict__ srp, const float* __restrict__ sip)
{
    int i = blockIdx.x * 256 + threadIdx.x;
    if (i < DIMN) {
        double sr = (double)(*srp);
        double si = (double)(*sip);
        double ln = log((double)(i + 1));
        d_diag[i] = exp(-sr * ln) * cos(si * ln);
    }
}

// Main kernel: 4 consecutive row elements per thread, float4 stores.
__global__ void __launch_bounds__(256)
nkaro_main(const float* __restrict__ srp, const float* __restrict__ sip,
           float4* __restrict__ out)
{
    unsigned t = blockIdx.x * 256u + threadIdx.x;     // grid covers DIM2/4 exactly
    unsigned base = t * 4u;
    int i = (int)(base >> 11);
    int j0 = (int)(base & (DIMN - 1));

    if (j0 + 3 < i - 5 || j0 > i + 5) {               // quad fully out of band
        out[t] = make_float4(0.0f, 0.0f, 0.0f, 0.0f);
        return;
    }

    float sr = *srp, si = *sip;
    float sabs = sqrtf(sr * sr + si * si);

    float v[4];
    #pragma unroll
    for (int e = 0; e < 4; ++e) {
        int j = j0 + e;
        int off = j - i;
        v[e] = (off < -5 || off > 5) ? 0.0f : band_re(i, j, sabs);
    }
    out[t] = make_float4(v[0], v[1], v[2], v[3]);
}

// Fallback for unexpected out_size: scalar, bounds-guarded.
__global__ void __launch_bounds__(256)
nkaro_scalar(const float* __restrict__ srp, const float* __restrict__ sip,
             float* __restrict__ out, unsigned total)
{
    unsigned idx = blockIdx.x * 256u + threadIdx.x;
    if (idx >= total) return;
    int i = (int)(idx >> 11);
    int j = (int)(idx & (DIMN - 1));
    int off = j - i;
    if (off < -5 || off > 5) { out[idx] = 0.0f; return; }
    float sr = *srp, si = *sip;
    out[idx] = band_re(i, j, sqrtf(sr * sr + si * si));
}

extern "C" void kernel_launch(void* const* d_in, const int* in_sizes, int n_in,
                              void* d_out, int out_size)
{
    (void)in_sizes; (void)n_in;
    const float* sr = (const float*)d_in[0];
    const float* si = (const float*)d_in[1];

    nkaro_diag<<<(DIMN + 255) / 256, 256>>>(sr, si);

    if (out_size == DIM2) {
        nkaro_main<<<DIM2 / 4 / 256, 256>>>(sr, si, (float4*)d_out);
    } else {
        unsigned total = (unsigned)out_size;
        unsigned blocks = (total + 255u) / 256u;
        if (blocks == 0) blocks = 1;
        nkaro_scalar<<<blocks, 256>>>(sr, si, (float*)d_out, total);
    }
}